// round 1
// baseline (speedup 1.0000x reference)
#include <cuda_runtime.h>
#include <cuda_bf16.h>
#include <math.h>

// ---------------- problem constants (dataset is fixed) ----------------
#define NN 50000      // nodes
#define EE 600000     // edges
#define DH 128        // feature dim
#define GG 512        // graphs

// ---------------- device scratch (no allocation allowed) ----------------
__device__ float d_agg [NN * DH];
__device__ float d_hpre[NN * DH];
__device__ float d_h1  [NN * DH];
__device__ float d_h2  [NN * DH];
__device__ float d_pool[GG * 4 * DH];     // [G, 512] = a1|a2|m1|m2
__device__ float d_r1  [GG * 4 * DH];     // readout hidden [G, 512]
__device__ int   d_src [EE];
__device__ int   d_dst [EE];
__device__ int   d_batch[NN];
__device__ int   d_gstart[GG];
__device__ int   d_gend [GG];
__device__ float d_colstats[2 * DH];      // sum | sumsq
__device__ float d_scale[DH];
__device__ float d_shift[DH];
__device__ int   d_flag_edge;
__device__ int   d_flag_batch;

// ---------------- dtype detection (int64 vs int32 indices) ----------------
__global__ void detect_k(const void* edge, const void* batch,
                         int e2cnt, int ncnt, long long nodeMax, long long gMax) {
    if (threadIdx.x != 0 || blockIdx.x != 0) return;
    const long long* e64 = (const long long*)edge;
    const long long* b64 = (const long long*)batch;
    int ok = 1;
    long long cnt = e2cnt / 2;   // only probe first half if data were int32
    for (int i = 0; i < 256; i++) {
        long long idx = (cnt - 1) * (long long)i / 255;
        long long v = e64[idx];
        if (v < 0 || v >= nodeMax) { ok = 0; break; }
    }
    d_flag_edge = ok;
    ok = 1;
    cnt = ncnt / 2;
    for (int i = 0; i < 256; i++) {
        long long idx = (cnt - 1) * (long long)i / 255;
        long long v = b64[idx];
        if (v < 0 || v >= gMax) { ok = 0; break; }
    }
    d_flag_batch = ok;
}

__global__ void convert_k(const void* edge, const void* batch, int Ecnt, int Ncnt) {
    int i = blockIdx.x * blockDim.x + threadIdx.x;
    int total = 2 * Ecnt + Ncnt;
    if (i >= total) return;
    int fe = d_flag_edge, fb = d_flag_batch;
    if (i < 2 * Ecnt) {
        long long v = fe ? ((const long long*)edge)[i]
                         : (long long)((const int*)edge)[i];
        if (i < Ecnt) d_src[i] = (int)v;
        else          d_dst[i - Ecnt] = (int)v;
    } else {
        int j = i - 2 * Ecnt;
        long long v = fb ? ((const long long*)batch)[j]
                         : (long long)((const int*)batch)[j];
        d_batch[j] = (int)v;
    }
}

// ---------------- segment bounds (batch is sorted) ----------------
__global__ void init_bounds_k(int Ncnt) {
    int g = blockIdx.x * blockDim.x + threadIdx.x;
    if (g < GG) { d_gstart[g] = Ncnt; d_gend[g] = 0; }
}
__global__ void fill_bounds_k(int Ncnt) {
    int i = blockIdx.x * blockDim.x + threadIdx.x;
    if (i >= Ncnt) return;
    int g = d_batch[i];
    atomicMin(&d_gstart[g], i);
    atomicMax(&d_gend[g], i + 1);
}

// ---------------- zero fill ----------------
__global__ void zero_k(float* p, int n) {
    int i = blockIdx.x * blockDim.x + threadIdx.x;
    int stride = gridDim.x * blockDim.x;
    for (; i < n; i += stride) p[i] = 0.0f;
}

// ---------------- edge scatter: agg[dst] += x[src] ----------------
__global__ void scatter_k(const float* __restrict__ x, float* __restrict__ agg, int Ecnt) {
    int t = blockIdx.x * blockDim.x + threadIdx.x;
    int e = t >> 5, lane = t & 31;
    if (e >= Ecnt) return;
    int s = d_src[e], d = d_dst[e];
    float4 v = *((const float4*)(x + (size_t)s * DH) + lane);
    float* p = agg + (size_t)d * DH + (size_t)lane * 4;
    atomicAdd(p + 0, v.x);
    atomicAdd(p + 1, v.y);
    atomicAdd(p + 2, v.z);
    atomicAdd(p + 3, v.w);
}

// ---------------- tiled SGEMM, BM=BN=128, BK=16, 256 threads, 8x8/thread ----
// MODE 0: A := A + A2 (elementwise), epilogue: +bias, write C, accumulate column stats
// MODE 1: A := relu(scale[k]*A + shift[k]) on load, epilogue: relu(+bias)
// MODE 2: plain A, epilogue: relu(+bias)
template<int MODE>
__global__ __launch_bounds__(256)
void gemm_k(const float* __restrict__ A, const float* __restrict__ A2,
            const float* __restrict__ B, const float* __restrict__ bias,
            float* __restrict__ C, int M, int K, int NC,
            const float* __restrict__ scale, const float* __restrict__ shift,
            float* __restrict__ colstats)
{
    __shared__ float As[16][128];
    __shared__ float Bs[16][132];
    const int tid = threadIdx.x;
    const int row0 = blockIdx.x * 128;
    const int col0 = blockIdx.y * 128;
    const int tx = tid & 15;       // column group
    const int ty = tid >> 4;       // row group

    float acc[8][8];
    #pragma unroll
    for (int i = 0; i < 8; i++)
        #pragma unroll
        for (int j = 0; j < 8; j++) acc[i][j] = 0.0f;

    for (int k0 = 0; k0 < K; k0 += 16) {
        // load A tile (128 rows x 16 k) transposed into As[k][m]
        #pragma unroll
        for (int li = 0; li < 2; li++) {
            int e = tid * 2 + li;
            int r = e >> 2;
            int c = (e & 3) * 4;
            int grow = row0 + r;
            float4 v = make_float4(0.f, 0.f, 0.f, 0.f);
            if (grow < M) {
                v = *(const float4*)(A + (size_t)grow * K + k0 + c);
                if (MODE == 0) {
                    float4 u = *(const float4*)(A2 + (size_t)grow * K + k0 + c);
                    v.x += u.x; v.y += u.y; v.z += u.z; v.w += u.w;
                }
                if (MODE == 1) {
                    v.x = fmaxf(fmaf(scale[k0 + c + 0], v.x, shift[k0 + c + 0]), 0.f);
                    v.y = fmaxf(fmaf(scale[k0 + c + 1], v.y, shift[k0 + c + 1]), 0.f);
                    v.z = fmaxf(fmaf(scale[k0 + c + 2], v.z, shift[k0 + c + 2]), 0.f);
                    v.w = fmaxf(fmaf(scale[k0 + c + 3], v.w, shift[k0 + c + 3]), 0.f);
                }
            }
            As[c + 0][r] = v.x; As[c + 1][r] = v.y;
            As[c + 2][r] = v.z; As[c + 3][r] = v.w;
        }
        // load B tile (16 k x 128 cols)
        #pragma unroll
        for (int li = 0; li < 2; li++) {
            int e = tid * 2 + li;
            int br = e >> 5;
            int bc = (e & 31) * 4;
            float4 v = *(const float4*)(B + (size_t)(k0 + br) * NC + col0 + bc);
            *(float4*)&Bs[br][bc] = v;
        }
        __syncthreads();
        #pragma unroll
        for (int kk = 0; kk < 16; kk++) {
            float ra[8], rb[8];
            #pragma unroll
            for (int i = 0; i < 8; i++) ra[i] = As[kk][ty * 8 + i];
            #pragma unroll
            for (int j = 0; j < 8; j++) rb[j] = Bs[kk][tx * 8 + j];
            #pragma unroll
            for (int i = 0; i < 8; i++)
                #pragma unroll
                for (int j = 0; j < 8; j++)
                    acc[i][j] = fmaf(ra[i], rb[j], acc[i][j]);
        }
        __syncthreads();
    }

    // epilogue
    #pragma unroll
    for (int j = 0; j < 8; j++) {
        int col = col0 + tx * 8 + j;
        float b = bias[col];
        float csum = 0.f, csq = 0.f;
        #pragma unroll
        for (int i = 0; i < 8; i++) {
            int row = row0 + ty * 8 + i;
            if (row < M) {
                float c = acc[i][j] + b;
                if (MODE == 1 || MODE == 2) c = fmaxf(c, 0.f);
                C[(size_t)row * NC + col] = c;
                if (MODE == 0) { csum += c; csq += c * c; }
            }
        }
        if (MODE == 0) {
            atomicAdd(&colstats[col], csum);
            atomicAdd(&colstats[DH + col], csq);
        }
    }
}

// ---------------- BN finalize ----------------
__global__ void bn_finalize_k(const float* __restrict__ g, const float* __restrict__ be, int M) {
    int j = threadIdx.x;
    if (j >= DH) return;
    float mu = d_colstats[j] / (float)M;
    float var = d_colstats[DH + j] / (float)M - mu * mu;
    float sc = g[j] * rsqrtf(var + 1e-5f);
    d_scale[j] = sc;
    d_shift[j] = be[j] - mu * sc;
}

// ---------------- pooling: one block per graph ----------------
__global__ void pool_k(const float* __restrict__ h, int off_sum, int off_max) {
    int gph = blockIdx.x;
    int j = threadIdx.x;   // 128
    int s = d_gstart[gph], e = d_gend[gph];
    float sum = 0.f, mx = 0.f;
    int r = s;
    for (; r + 4 <= e; r += 4) {
        float v0 = h[(size_t)(r + 0) * DH + j];
        float v1 = h[(size_t)(r + 1) * DH + j];
        float v2 = h[(size_t)(r + 2) * DH + j];
        float v3 = h[(size_t)(r + 3) * DH + j];
        sum += v0 + v1 + v2 + v3;
        mx = fmaxf(mx, fmaxf(fmaxf(v0, v1), fmaxf(v2, v3)));
    }
    for (; r < e; r++) {
        float v = h[(size_t)r * DH + j];
        sum += v; mx = fmaxf(mx, v);
    }
    // h is post-ReLU (>=0); empty segments -> 0 matches reference's isfinite fixup
    d_pool[(size_t)gph * 512 + off_sum + j] = sum;
    d_pool[(size_t)gph * 512 + off_max + j] = mx;
}

// ---------------- final linear + sigmoid ----------------
__global__ void final_k(const float* __restrict__ r1, const float* __restrict__ w,
                        const float* __restrict__ b, float* __restrict__ out, int out_size) {
    int gph = blockIdx.x;
    int tid = threadIdx.x;   // 128
    float s = 0.f;
    #pragma unroll
    for (int k = tid; k < 512; k += 128) s += r1[(size_t)gph * 512 + k] * w[k];
    __shared__ float red[128];
    red[tid] = s;
    __syncthreads();
    for (int st = 64; st > 0; st >>= 1) {
        if (tid < st) red[tid] += red[tid + st];
        __syncthreads();
    }
    if (tid == 0) {
        float h = red[0] + b[0];
        float sg = 1.f / (1.f + expf(-h));
        out[gph] = sg;
        if (out_size >= 2 * GG) out[GG + gph] = h;
    }
}

// ---------------- host launch ----------------
extern "C" void kernel_launch(void* const* d_in, const int* in_sizes, int n_in,
                              void* d_out, int out_size) {
    const float* x      = (const float*)d_in[0];
    const void*  edge   = d_in[1];
    const void*  batch  = d_in[2];
    const float* c1_W1  = (const float*)d_in[3];
    const float* c1_b1  = (const float*)d_in[4];
    const float* c1_g   = (const float*)d_in[5];
    const float* c1_be  = (const float*)d_in[6];
    const float* c1_W2  = (const float*)d_in[7];
    const float* c1_b2  = (const float*)d_in[8];
    const float* c2_W1  = (const float*)d_in[9];
    const float* c2_b1  = (const float*)d_in[10];
    const float* c2_g   = (const float*)d_in[11];
    const float* c2_be  = (const float*)d_in[12];
    const float* c2_W2  = (const float*)d_in[13];
    const float* c2_b2  = (const float*)d_in[14];
    const float* lin1_W = (const float*)d_in[15];
    const float* lin1_b = (const float*)d_in[16];
    const float* lin2_W = (const float*)d_in[17];
    const float* lin2_b = (const float*)d_in[18];

    const int N = in_sizes[0] / DH;       // 50000
    const int E = in_sizes[1] / 2;        // 600000
    float* out = (float*)d_out;

    float *agg, *hpre, *h1, *h2, *pool, *r1, *colstats;
    cudaGetSymbolAddress((void**)&agg,      d_agg);
    cudaGetSymbolAddress((void**)&hpre,     d_hpre);
    cudaGetSymbolAddress((void**)&h1,       d_h1);
    cudaGetSymbolAddress((void**)&h2,       d_h2);
    cudaGetSymbolAddress((void**)&pool,     d_pool);
    cudaGetSymbolAddress((void**)&r1,       d_r1);
    cudaGetSymbolAddress((void**)&colstats, d_colstats);

    // 1) index dtype detection + conversion
    detect_k<<<1, 32>>>(edge, batch, 2 * E, N, (long long)N, (long long)GG);
    {
        int total = 2 * E + N;
        convert_k<<<(total + 255) / 256, 256>>>(edge, batch, E, N);
    }

    // 2) per-graph segment bounds (batch sorted; reused by both convs)
    init_bounds_k<<<(GG + 255) / 256, 256>>>(N);
    fill_bounds_k<<<(N + 255) / 256, 256>>>(N);

    const int gemm_gx = (N + 127) / 128;
    const dim3 gemm_grid(gemm_gx, 1);
    const int scat_blocks = (E * 32 + 255) / 256;

    // ---- conv1 ----
    zero_k<<<2048, 256>>>(agg, N * DH);
    zero_k<<<1, 256>>>(colstats, 2 * DH);
    scatter_k<<<scat_blocks, 256>>>(x, agg, E);
    gemm_k<0><<<gemm_grid, 256>>>(agg, x, c1_W1, c1_b1, hpre, N, DH, DH,
                                  nullptr, nullptr, colstats);
    bn_finalize_k<<<1, DH>>>(c1_g, c1_be, N);
    {
        float* sc; float* sh;
        cudaGetSymbolAddress((void**)&sc, d_scale);
        cudaGetSymbolAddress((void**)&sh, d_shift);
        gemm_k<1><<<gemm_grid, 256>>>(hpre, nullptr, c1_W2, c1_b2, h1, N, DH, DH,
                                      sc, sh, nullptr);
    }
    pool_k<<<GG, DH>>>(h1, 0, 256);

    // ---- conv2 ----
    zero_k<<<2048, 256>>>(agg, N * DH);
    zero_k<<<1, 256>>>(colstats, 2 * DH);
    scatter_k<<<scat_blocks, 256>>>(h1, agg, E);
    gemm_k<0><<<gemm_grid, 256>>>(agg, h1, c2_W1, c2_b1, hpre, N, DH, DH,
                                  nullptr, nullptr, colstats);
    bn_finalize_k<<<1, DH>>>(c2_g, c2_be, N);
    {
        float* sc; float* sh;
        cudaGetSymbolAddress((void**)&sc, d_scale);
        cudaGetSymbolAddress((void**)&sh, d_shift);
        gemm_k<1><<<gemm_grid, 256>>>(hpre, nullptr, c2_W2, c2_b2, h2, N, DH, DH,
                                      sc, sh, nullptr);
    }
    pool_k<<<GG, DH>>>(h2, 128, 384);

    // ---- readout ----
    {
        dim3 grid((GG + 127) / 128, 4);   // M=512, NC=512
        gemm_k<2><<<grid, 256>>>(pool, nullptr, lin1_W, lin1_b, r1, GG, 512, 512,
                                 nullptr, nullptr, nullptr);
    }
    final_k<<<GG, 128>>>(r1, lin2_W, lin2_b, out, out_size);
}